// round 2
// baseline (speedup 1.0000x reference)
#include <cuda_runtime.h>
#include <cuda_bf16.h>

#define NN   100000
#define NE   1600000
#define NET  (NE + NN)      // edges + self loops
#define FF   256
#define HC   128
#define NH   4

// ---------------- scratch (device globals; no runtime allocation) ----------
__device__ float g_h[(size_t)NN * HC];      // projected features  [N,128]
__device__ float g_asrc[NN * NH];           // per-node src attention half [N,4]
__device__ float g_adst[NN * NH];           // per-node dst attention half [N,4]
__device__ int   g_deg[NN];
__device__ int   g_off[NN + 1];
__device__ int   g_cur[NN];
__device__ int   g_srt[NET];                // src node id per CSR slot (by dst)
__device__ int   g_bs[128];                 // block sums for scan

// ---------------- CSR build ------------------------------------------------
__global__ void k_init_deg() {
    int i = blockIdx.x * blockDim.x + threadIdx.x;
    if (i < NN) g_deg[i] = 1;               // self loop
}

__global__ void k_hist(const int* __restrict__ ei) {
    int e = blockIdx.x * blockDim.x + threadIdx.x;
    if (e < NE) atomicAdd(&g_deg[ei[NE + e]], 1);
}

__global__ void k_scan1() {
    __shared__ int sh[1024];
    int t = threadIdx.x;
    int i = blockIdx.x * 1024 + t;
    int v = (i < NN) ? g_deg[i] : 0;
    sh[t] = v;
    __syncthreads();
    #pragma unroll
    for (int off = 1; off < 1024; off <<= 1) {
        int x = sh[t];
        int y = (t >= off) ? sh[t - off] : 0;
        __syncthreads();
        sh[t] = x + y;
        __syncthreads();
    }
    int excl = (t == 0) ? 0 : sh[t - 1];
    if (i < NN) g_off[i] = excl;
    if (t == 1023) g_bs[blockIdx.x] = sh[1023];
}

__global__ void k_scan2(int nb) {
    if (threadIdx.x == 0) {
        int run = 0;
        for (int b = 0; b < nb; b++) { int v = g_bs[b]; g_bs[b] = run; run += v; }
    }
}

__global__ void k_scan3() {
    int i = blockIdx.x * blockDim.x + threadIdx.x;
    if (i < NN) {
        int o = g_off[i] + g_bs[i >> 10];
        g_off[i] = o;
        g_cur[i] = o;
        if (i == 0) g_off[NN] = NET;
    }
}

__global__ void k_fill(const int* __restrict__ ei) {
    int idx = blockIdx.x * blockDim.x + threadIdx.x;
    if (idx >= NET) return;
    int dst, src;
    if (idx < NE) { src = ei[idx]; dst = ei[NE + idx]; }
    else          { src = idx - NE; dst = idx - NE; }       // self loop
    int pos = atomicAdd(&g_cur[dst], 1);
    g_srt[pos] = src;
}

// ---------------- GEMM: h = x @ W, fused a_src / a_dst ---------------------
#define GTM 128
#define GKC 16

__device__ __forceinline__ void fma4(float4& acc, float s, const float4& v) {
    acc.x = fmaf(s, v.x, acc.x);
    acc.y = fmaf(s, v.y, acc.y);
    acc.z = fmaf(s, v.z, acc.z);
    acc.w = fmaf(s, v.w, acc.w);
}

__device__ __forceinline__ float dot4(float4 a, float4 b) {
    return a.x * b.x + a.y * b.y + a.z * b.z + a.w * b.w;
}

__global__ void __launch_bounds__(256, 2) k_gemm(
    const float* __restrict__ x, const float* __restrict__ W,
    const float* __restrict__ att_s, const float* __restrict__ att_d)
{
    __shared__ float sx[GKC][GTM];
    __shared__ float sw[GKC][HC];
    __shared__ float sa[GTM][NH];
    __shared__ float sd[GTM][NH];

    int tid = threadIdx.x;
    int tx = tid & 15, ty = tid >> 4;
    int row0 = blockIdx.x * GTM;
    int c0 = tx * 4, c1 = c0 + 64;

    float4 accA[8], accB[8];
    #pragma unroll
    for (int r = 0; r < 8; r++) {
        accA[r] = make_float4(0.f, 0.f, 0.f, 0.f);
        accB[r] = make_float4(0.f, 0.f, 0.f, 0.f);
    }

    for (int kc = 0; kc < FF; kc += GKC) {
        // x tile: 128 rows x 16 k, transposed into sx[k][row]
        #pragma unroll
        for (int p = 0; p < 2; p++) {
            int row = p * 64 + (tid >> 2);
            int kk = (tid & 3) * 4;
            float4 v = make_float4(0.f, 0.f, 0.f, 0.f);
            if (row0 + row < NN)
                v = *(const float4*)&x[(size_t)(row0 + row) * FF + kc + kk];
            sx[kk + 0][row] = v.x; sx[kk + 1][row] = v.y;
            sx[kk + 2][row] = v.z; sx[kk + 3][row] = v.w;
        }
        // W tile: 16 k x 128 cols
        {
            int k = tid >> 4;
            int c = (tid & 15) * 8;
            *(float4*)&sw[k][c]     = *(const float4*)&W[(kc + k) * HC + c];
            *(float4*)&sw[k][c + 4] = *(const float4*)&W[(kc + k) * HC + c + 4];
        }
        __syncthreads();
        #pragma unroll
        for (int k = 0; k < GKC; k++) {
            float4 xv0 = *(float4*)&sx[k][ty * 4];
            float4 xv1 = *(float4*)&sx[k][64 + ty * 4];
            float4 w0 = *(float4*)&sw[k][c0];
            float4 w1 = *(float4*)&sw[k][c1];
            fma4(accA[0], xv0.x, w0); fma4(accB[0], xv0.x, w1);
            fma4(accA[1], xv0.y, w0); fma4(accB[1], xv0.y, w1);
            fma4(accA[2], xv0.z, w0); fma4(accB[2], xv0.z, w1);
            fma4(accA[3], xv0.w, w0); fma4(accB[3], xv0.w, w1);
            fma4(accA[4], xv1.x, w0); fma4(accB[4], xv1.x, w1);
            fma4(accA[5], xv1.y, w0); fma4(accB[5], xv1.y, w1);
            fma4(accA[6], xv1.z, w0); fma4(accB[6], xv1.z, w1);
            fma4(accA[7], xv1.w, w0); fma4(accB[7], xv1.w, w1);
        }
        __syncthreads();
    }

    // epilogue: write h, accumulate per-row attention halves
    for (int q = tid; q < GTM * NH; q += 256) { sa[q >> 2][q & 3] = 0.f; sd[q >> 2][q & 3] = 0.f; }
    __syncthreads();

    float4 as0 = *(const float4*)&att_s[c0];
    float4 as1 = *(const float4*)&att_s[c1];
    float4 ad0 = *(const float4*)&att_d[c0];
    float4 ad1 = *(const float4*)&att_d[c1];
    int h0 = tx >> 3, h1 = (tx >> 3) + 2;

    #pragma unroll
    for (int r = 0; r < 8; r++) {
        int row = (r < 4) ? (ty * 4 + r) : (64 + ty * 4 + (r - 4));
        int grow = row0 + row;
        if (grow < NN) {
            *(float4*)&g_h[(size_t)grow * HC + c0] = accA[r];
            *(float4*)&g_h[(size_t)grow * HC + c1] = accB[r];
        }
        atomicAdd(&sa[row][h0], dot4(accA[r], as0));
        atomicAdd(&sa[row][h1], dot4(accB[r], as1));
        atomicAdd(&sd[row][h0], dot4(accA[r], ad0));
        atomicAdd(&sd[row][h1], dot4(accB[r], ad1));
    }
    __syncthreads();
    for (int q = tid; q < GTM * NH; q += 256) {
        int row = q >> 2, hh = q & 3;
        int grow = row0 + row;
        if (grow < NN) {
            g_asrc[grow * NH + hh] = sa[row][hh];
            g_adst[grow * NH + hh] = sd[row][hh];
        }
    }
}

// ---------------- per-node softmax + aggregate (warp per node) -------------
__device__ __forceinline__ float lrelu(float v) { return v > 0.f ? v : 0.2f * v; }
__device__ __forceinline__ float comp4(float4 v, int i) {
    return i == 0 ? v.x : i == 1 ? v.y : i == 2 ? v.z : v.w;
}

__global__ void __launch_bounds__(256) k_gat(
    const float* __restrict__ bias, float* __restrict__ out)
{
    int w = (blockIdx.x * blockDim.x + threadIdx.x) >> 5;
    int lane = threadIdx.x & 31;
    if (w >= NN) return;

    int o0 = g_off[w];
    int d = g_off[w + 1] - o0;
    float4 adst = *(const float4*)&g_adst[w * NH];

    // pass 1: per-head max; cache first chunk (avg degree 17 < 32)
    float4 m = make_float4(-1e30f, -1e30f, -1e30f, -1e30f);
    int j0 = -1;
    float4 e0 = m;
    for (int base = 0; base < d; base += 32) {
        int idx = base + lane;
        int j = (idx < d) ? g_srt[o0 + idx] : -1;
        if (base == 0) j0 = j;
        if (j >= 0) {
            float4 as = *(const float4*)&g_asrc[j * NH];
            float4 e;
            e.x = lrelu(as.x + adst.x); e.y = lrelu(as.y + adst.y);
            e.z = lrelu(as.z + adst.z); e.w = lrelu(as.w + adst.w);
            if (base == 0) e0 = e;
            m.x = fmaxf(m.x, e.x); m.y = fmaxf(m.y, e.y);
            m.z = fmaxf(m.z, e.z); m.w = fmaxf(m.w, e.w);
        }
    }
    #pragma unroll
    for (int s = 16; s; s >>= 1) {
        m.x = fmaxf(m.x, __shfl_xor_sync(0xffffffffu, m.x, s));
        m.y = fmaxf(m.y, __shfl_xor_sync(0xffffffffu, m.y, s));
        m.z = fmaxf(m.z, __shfl_xor_sync(0xffffffffu, m.z, s));
        m.w = fmaxf(m.w, __shfl_xor_sync(0xffffffffu, m.w, s));
    }

    // pass 2: softmax denominator
    float4 sm = make_float4(0.f, 0.f, 0.f, 0.f);
    if (j0 >= 0) {
        sm.x = __expf(e0.x - m.x); sm.y = __expf(e0.y - m.y);
        sm.z = __expf(e0.z - m.z); sm.w = __expf(e0.w - m.w);
    }
    for (int base = 32; base < d; base += 32) {
        int idx = base + lane;
        if (idx < d) {
            int j = g_srt[o0 + idx];
            float4 as = *(const float4*)&g_asrc[j * NH];
            sm.x += __expf(lrelu(as.x + adst.x) - m.x);
            sm.y += __expf(lrelu(as.y + adst.y) - m.y);
            sm.z += __expf(lrelu(as.z + adst.z) - m.z);
            sm.w += __expf(lrelu(as.w + adst.w) - m.w);
        }
    }
    #pragma unroll
    for (int s = 16; s; s >>= 1) {
        sm.x += __shfl_xor_sync(0xffffffffu, sm.x, s);
        sm.y += __shfl_xor_sync(0xffffffffu, sm.y, s);
        sm.z += __shfl_xor_sync(0xffffffffu, sm.z, s);
        sm.w += __shfl_xor_sync(0xffffffffu, sm.w, s);
    }

    int head = lane >> 3;                      // lane owns channels lane*4..lane*4+3
    float mh = comp4(m, head);
    float ih = 1.f / (comp4(sm, head) + 1e-16f);
    float adh = comp4(adst, head);

    // pass 3: weighted aggregate of h[src]; 512B coalesced gather per edge
    float4 acc = make_float4(0.f, 0.f, 0.f, 0.f);
    for (int base = 0; base < d; base += 32) {
        int jl = (base == 0) ? j0
                             : ((base + lane < d) ? g_srt[o0 + base + lane] : -1);
        int cnt = min(32, d - base);
        for (int t = 0; t < cnt; t++) {
            int j = __shfl_sync(0xffffffffu, jl, t);
            float asj = g_asrc[j * NH + head];
            float eh = lrelu(asj + adh);
            float al = __expf(eh - mh) * ih;
            float4 hv = *(const float4*)&g_h[(size_t)j * HC + lane * 4];
            acc.x = fmaf(al, hv.x, acc.x);
            acc.y = fmaf(al, hv.y, acc.y);
            acc.z = fmaf(al, hv.z, acc.z);
            acc.w = fmaf(al, hv.w, acc.w);
        }
    }
    float4 b = *(const float4*)&bias[lane * 4];
    float4 o = make_float4(acc.x + b.x, acc.y + b.y, acc.z + b.z, acc.w + b.w);
    *(float4*)&out[(size_t)w * HC + lane * 4] = o;
}

// ---------------- launch ----------------------------------------------------
extern "C" void kernel_launch(void* const* d_in, const int* in_sizes, int n_in,
                              void* d_out, int out_size)
{
    const float* x     = (const float*)d_in[0];
    const int*   ei    = (const int*)d_in[1];
    const float* W     = (const float*)d_in[2];
    const float* att_s = (const float*)d_in[3];
    const float* att_d = (const float*)d_in[4];
    const float* bias  = (const float*)d_in[5];
    float* out = (float*)d_out;

    const int NB = (NN + 1023) / 1024;   // 98

    k_init_deg<<<(NN + 255) / 256, 256>>>();
    k_hist<<<(NE + 255) / 256, 256>>>(ei);
    k_scan1<<<NB, 1024>>>();
    k_scan2<<<1, 32>>>(NB);
    k_scan3<<<(NN + 255) / 256, 256>>>();
    k_fill<<<(NET + 255) / 256, 256>>>(ei);

    k_gemm<<<(NN + GTM - 1) / GTM, 256>>>(x, W, att_s, att_d);
    k_gat<<<(NN * 32 + 255) / 256, 256>>>(bias, out);
}

// round 4
// speedup vs baseline: 1.5440x; 1.5440x over previous
#include <cuda_runtime.h>
#include <cuda_bf16.h>
#include <cstdint>

#define NN   100000
#define NE   1600000
#define NET  (NE + NN)      // edges + self loops
#define FF   256
#define HC   128
#define NH   4

// ---------------- scratch (device globals; no runtime allocation) ----------
__device__ float g_h[(size_t)NN * HC];      // projected features  [N,128]
__device__ float g_asrc[NN * NH];           // per-node src attention half [N,4]
__device__ float g_adst[NN * NH];           // per-node dst attention half [N,4]
__device__ int   g_deg[NN];
__device__ int   g_off[NN + 1];
__device__ int   g_cur[NN];
__device__ int   g_srt[NET];                // src node id per CSR slot (by dst)
__device__ int   g_bs[128];                 // block sums for scan
__device__ __nv_bfloat16 g_wt_hi[HC * FF];  // W^T hi, K-major [n][k]
__device__ __nv_bfloat16 g_wt_lo[HC * FF];  // W^T lo

// ---------------- CSR build ------------------------------------------------
__global__ void k_init_deg() {
    int i = blockIdx.x * blockDim.x + threadIdx.x;
    if (i < NN) g_deg[i] = 1;               // self loop
}

__global__ void k_hist(const int* __restrict__ ei) {
    int e = blockIdx.x * blockDim.x + threadIdx.x;
    if (e < NE) atomicAdd(&g_deg[ei[NE + e]], 1);
}

__global__ void k_scan1() {
    __shared__ int sh[1024];
    int t = threadIdx.x;
    int i = blockIdx.x * 1024 + t;
    int v = (i < NN) ? g_deg[i] : 0;
    sh[t] = v;
    __syncthreads();
    #pragma unroll
    for (int off = 1; off < 1024; off <<= 1) {
        int x = sh[t];
        int y = (t >= off) ? sh[t - off] : 0;
        __syncthreads();
        sh[t] = x + y;
        __syncthreads();
    }
    int excl = (t == 0) ? 0 : sh[t - 1];
    if (i < NN) g_off[i] = excl;
    if (t == 1023) g_bs[blockIdx.x] = sh[1023];
}

__global__ void k_scan2() {                 // 1 block, 128 threads
    __shared__ int sh[128];
    int t = threadIdx.x;
    int v = (t < 98) ? g_bs[t] : 0;
    sh[t] = v;
    __syncthreads();
    #pragma unroll
    for (int off = 1; off < 128; off <<= 1) {
        int x = sh[t];
        int y = (t >= off) ? sh[t - off] : 0;
        __syncthreads();
        sh[t] = x + y;
        __syncthreads();
    }
    if (t < 98) g_bs[t] = sh[t] - v;        // exclusive
}

__global__ void k_scan3() {
    int i = blockIdx.x * blockDim.x + threadIdx.x;
    if (i < NN) {
        int o = g_off[i] + g_bs[i >> 10];
        g_off[i] = o;
        g_cur[i] = o;
        if (i == 0) g_off[NN] = NET;
    }
}

__global__ void k_fill(const int* __restrict__ ei) {
    int idx = blockIdx.x * blockDim.x + threadIdx.x;
    if (idx >= NET) return;
    int dst, src;
    if (idx < NE) { src = ei[idx]; dst = ei[NE + idx]; }
    else          { src = idx - NE; dst = idx - NE; }       // self loop
    int pos = atomicAdd(&g_cur[dst], 1);
    g_srt[pos] = src;
}

// ---------------- W prep: transpose + bf16 hi/lo split ----------------------
__global__ void k_prepw(const float* __restrict__ W) {
    int idx = blockIdx.x * blockDim.x + threadIdx.x;
    if (idx >= HC * FF) return;
    int n = idx >> 8, k = idx & 255;
    float v = W[k * HC + n];
    __nv_bfloat16 hi = __float2bfloat16(v);
    __nv_bfloat16 lo = __float2bfloat16(v - __bfloat162float(hi));
    g_wt_hi[idx] = hi;
    g_wt_lo[idx] = lo;
}

// ---------------- GEMM: mma.sync bf16 3-term fp32 emulation -----------------
// CTA tile M=64, N=128, K staged in chunks of 64.
// 8 warps = 2(m) x 4(n); warp tile 32x32 (one head of 32 cols).

#define LDA 72                 // padded row stride in halves (144B: conflict-free)
#define SO_AS 0                // float[128]
#define SO_AD 512              // float[128]
#define SO_SA 1024             // float[64][4]
#define SO_SD 2048             // float[64][4]
#define SO_AH 3072             // half[64][72]
#define SO_AL (SO_AH + 9216)
#define SO_BH (SO_AL + 9216)   // half[128][72]
#define SO_BL (SO_BH + 18432)
#define SO_TOT (SO_BL + 18432) // 58368 bytes

__device__ __forceinline__ uint32_t smem_u32(const void* p) {
    uint32_t a;
    asm("{ .reg .u64 t; cvta.to.shared.u64 t, %1; cvt.u32.u64 %0, t; }"
        : "=r"(a) : "l"(p));
    return a;
}

__device__ __forceinline__ void ldm_x4(uint32_t* r, uint32_t addr) {
    asm volatile("ldmatrix.sync.aligned.m8n8.x4.shared.b16 {%0,%1,%2,%3}, [%4];"
                 : "=r"(r[0]), "=r"(r[1]), "=r"(r[2]), "=r"(r[3]) : "r"(addr));
}

__device__ __forceinline__ void mma_bf16(float* d, const uint32_t* a, const uint32_t* b) {
    asm volatile(
        "mma.sync.aligned.m16n8k16.row.col.f32.bf16.bf16.f32 "
        "{%0,%1,%2,%3}, {%4,%5,%6,%7}, {%8,%9}, {%0,%1,%2,%3};"
        : "+f"(d[0]), "+f"(d[1]), "+f"(d[2]), "+f"(d[3])
        : "r"(a[0]), "r"(a[1]), "r"(a[2]), "r"(a[3]), "r"(b[0]), "r"(b[1]));
}

__device__ __forceinline__ uint32_t pk(__nv_bfloat16 a, __nv_bfloat16 b) {
    return (uint32_t)__bfloat16_as_ushort(a) | ((uint32_t)__bfloat16_as_ushort(b) << 16);
}

__global__ void __launch_bounds__(256, 2) k_gemm(
    const float* __restrict__ x,
    const float* __restrict__ att_s, const float* __restrict__ att_d)
{
    extern __shared__ char sm[];
    uint32_t smb = smem_u32(sm);
    float* sAs = (float*)(sm + SO_AS);
    float* sAd = (float*)(sm + SO_AD);
    float* sa  = (float*)(sm + SO_SA);
    float* sd  = (float*)(sm + SO_SD);

    int tid = threadIdx.x;
    int wid = tid >> 5, lane = tid & 31;
    int wm = wid >> 2, wn = wid & 3;       // warp grid 2x4
    int row0 = blockIdx.x * 64;

    if (tid < HC) { sAs[tid] = att_s[tid]; sAd[tid] = att_d[tid]; }
    if (tid < 256) { sa[tid] = 0.f; sd[tid] = 0.f; }

    float acc[2][4][4];
    #pragma unroll
    for (int tm = 0; tm < 2; tm++)
        #pragma unroll
        for (int tn = 0; tn < 4; tn++)
            #pragma unroll
            for (int q = 0; q < 4; q++) acc[tm][tn][q] = 0.f;

    // fragment smem addresses (byte offsets), fixed per thread, vary by kk
    uint32_t a_row = (uint32_t)(wm * 32 + (lane & 15));
    uint32_t a_kh  = (uint32_t)((lane >> 4) << 3);
    uint32_t b_row = (uint32_t)(wn * 32 + (lane & 7) + ((lane >> 4) << 3));
    uint32_t b_kh  = (uint32_t)(((lane >> 3) & 1) << 3);

    for (int kc = 0; kc < FF; kc += 64) {
        // ---- stage A: x[row0..row0+63][kc..kc+63] -> hi/lo bf16 ----
        #pragma unroll
        for (int it = 0; it < 4; it++) {
            int i = tid + it * 256;
            int r = i >> 4, g = i & 15;
            float4 v = make_float4(0.f, 0.f, 0.f, 0.f);
            int grow = row0 + r;
            if (grow < NN)
                v = *(const float4*)&x[(size_t)grow * FF + kc + g * 4];
            __nv_bfloat16 h0 = __float2bfloat16(v.x), h1 = __float2bfloat16(v.y);
            __nv_bfloat16 h2 = __float2bfloat16(v.z), h3 = __float2bfloat16(v.w);
            uint2 hv = make_uint2(pk(h0, h1), pk(h2, h3));
            uint2 lv = make_uint2(
                pk(__float2bfloat16(v.x - __bfloat162float(h0)),
                   __float2bfloat16(v.y - __bfloat162float(h1))),
                pk(__float2bfloat16(v.z - __bfloat162float(h2)),
                   __float2bfloat16(v.w - __bfloat162float(h3))));
            uint32_t off = (uint32_t)(r * LDA + g * 4) * 2;
            *(uint2*)(sm + SO_AH + off) = hv;
            *(uint2*)(sm + SO_AL + off) = lv;
        }
        // ---- stage B: W^T[n][kc..kc+63] hi/lo ----
        #pragma unroll
        for (int it = 0; it < 4; it++) {
            int i = tid + it * 256;
            int n = i >> 3, g = i & 7;
            uint4 hv = *(const uint4*)&g_wt_hi[n * FF + kc + g * 8];
            uint4 lv = *(const uint4*)&g_wt_lo[n * FF + kc + g * 8];
            uint32_t off = (uint32_t)(n * LDA + g * 8) * 2;
            *(uint4*)(sm + SO_BH + off) = hv;
            *(uint4*)(sm + SO_BL + off) = lv;
        }
        __syncthreads();

        #pragma unroll
        for (int kk = 0; kk < 4; kk++) {
            uint32_t akb = (uint32_t)(kk * 16);
            uint32_t ah[2][4], al[2][4], bh[4][2], bl[4][2];
            #pragma unroll
            for (int tm = 0; tm < 2; tm++) {
                uint32_t off = ((a_row + tm * 16) * LDA + akb + a_kh) * 2;
                ldm_x4(ah[tm], smb + SO_AH + off);
                ldm_x4(al[tm], smb + SO_AL + off);
            }
            #pragma unroll
            for (int pr = 0; pr < 2; pr++) {
                uint32_t off = ((b_row + pr * 16) * LDA + akb + b_kh) * 2;
                uint32_t t4[4];
                ldm_x4(t4, smb + SO_BH + off);
                bh[pr * 2][0] = t4[0]; bh[pr * 2][1] = t4[1];
                bh[pr * 2 + 1][0] = t4[2]; bh[pr * 2 + 1][1] = t4[3];
                ldm_x4(t4, smb + SO_BL + off);
                bl[pr * 2][0] = t4[0]; bl[pr * 2][1] = t4[1];
                bl[pr * 2 + 1][0] = t4[2]; bl[pr * 2 + 1][1] = t4[3];
            }
            #pragma unroll
            for (int tm = 0; tm < 2; tm++)
                #pragma unroll
                for (int tn = 0; tn < 4; tn++) {
                    mma_bf16(acc[tm][tn], ah[tm], bh[tn]);
                    mma_bf16(acc[tm][tn], al[tm], bh[tn]);
                    mma_bf16(acc[tm][tn], ah[tm], bl[tn]);
                }
        }
        __syncthreads();
    }

    // ---- epilogue: write h, fused attention halves ----
    int qr = lane >> 2, qc = lane & 3;
    #pragma unroll
    for (int tm = 0; tm < 2; tm++) {
        #pragma unroll
        for (int half = 0; half < 2; half++) {
            int r = wm * 32 + tm * 16 + qr + half * 8;
            int grow = row0 + r;
            float ps = 0.f, pd = 0.f;
            #pragma unroll
            for (int tn = 0; tn < 4; tn++) {
                float c0 = acc[tm][tn][half * 2];
                float c1 = acc[tm][tn][half * 2 + 1];
                int col = wn * 32 + tn * 8 + qc * 2;
                ps = fmaf(c0, sAs[col], fmaf(c1, sAs[col + 1], ps));
                pd = fmaf(c0, sAd[col], fmaf(c1, sAd[col + 1], pd));
                if (grow < NN)
                    *(float2*)&g_h[(size_t)grow * HC + col] = make_float2(c0, c1);
            }
            atomicAdd(&sa[r * NH + wn], ps);
            atomicAdd(&sd[r * NH + wn], pd);
        }
    }
    __syncthreads();
    if (tid < 256) {
        int r = tid >> 2, hh = tid & 3;
        int grow = row0 + r;
        if (grow < NN) {
            g_asrc[grow * NH + hh] = sa[r * NH + hh];
            g_adst[grow * NH + hh] = sd[r * NH + hh];
        }
    }
}

// ---------------- per-node softmax + aggregate (warp per node) -------------
__device__ __forceinline__ float lrelu(float v) { return v > 0.f ? v : 0.2f * v; }
__device__ __forceinline__ float comp4(float4 v, int i) {
    return i == 0 ? v.x : i == 1 ? v.y : i == 2 ? v.z : v.w;
}

__global__ void __launch_bounds__(256) k_gat(
    const float* __restrict__ bias, float* __restrict__ out)
{
    int w = (blockIdx.x * blockDim.x + threadIdx.x) >> 5;
    int lane = threadIdx.x & 31;
    if (w >= NN) return;

    int o0 = g_off[w];
    int d = g_off[w + 1] - o0;
    float4 adst = *(const float4*)&g_adst[w * NH];

    // pass 1: per-head max; cache first chunk (avg degree 17 < 32)
    float4 m = make_float4(-1e30f, -1e30f, -1e30f, -1e30f);
    int j0 = -1;
    float4 e0 = m;
    for (int base = 0; base < d; base += 32) {
        int idx = base + lane;
        int j = (idx < d) ? g_srt[o0 + idx] : -1;
        if (base == 0) j0 = j;
        if (j >= 0) {
            float4 as = *(const float4*)&g_asrc[j * NH];
            float4 e;
            e.x = lrelu(as.x + adst.x); e.y = lrelu(as.y + adst.y);
            e.z = lrelu(as.z + adst.z); e.w = lrelu(as.w + adst.w);
            if (base == 0) e0 = e;
            m.x = fmaxf(m.x, e.x); m.y = fmaxf(m.y, e.y);
            m.z = fmaxf(m.z, e.z); m.w = fmaxf(m.w, e.w);
        }
    }
    #pragma unroll
    for (int s = 16; s; s >>= 1) {
        m.x = fmaxf(m.x, __shfl_xor_sync(0xffffffffu, m.x, s));
        m.y = fmaxf(m.y, __shfl_xor_sync(0xffffffffu, m.y, s));
        m.z = fmaxf(m.z, __shfl_xor_sync(0xffffffffu, m.z, s));
        m.w = fmaxf(m.w, __shfl_xor_sync(0xffffffffu, m.w, s));
    }

    // pass 2: softmax denominator
    float4 smv = make_float4(0.f, 0.f, 0.f, 0.f);
    if (j0 >= 0) {
        smv.x = __expf(e0.x - m.x); smv.y = __expf(e0.y - m.y);
        smv.z = __expf(e0.z - m.z); smv.w = __expf(e0.w - m.w);
    }
    for (int base = 32; base < d; base += 32) {
        int idx = base + lane;
        if (idx < d) {
            int j = g_srt[o0 + idx];
            float4 as = *(const float4*)&g_asrc[j * NH];
            smv.x += __expf(lrelu(as.x + adst.x) - m.x);
            smv.y += __expf(lrelu(as.y + adst.y) - m.y);
            smv.z += __expf(lrelu(as.z + adst.z) - m.z);
            smv.w += __expf(lrelu(as.w + adst.w) - m.w);
        }
    }
    #pragma unroll
    for (int s = 16; s; s >>= 1) {
        smv.x += __shfl_xor_sync(0xffffffffu, smv.x, s);
        smv.y += __shfl_xor_sync(0xffffffffu, smv.y, s);
        smv.z += __shfl_xor_sync(0xffffffffu, smv.z, s);
        smv.w += __shfl_xor_sync(0xffffffffu, smv.w, s);
    }

    int head = lane >> 3;                      // lane owns channels lane*4..lane*4+3
    float mh = comp4(m, head);
    float ih = 1.f / (comp4(smv, head) + 1e-16f);
    float adh = comp4(adst, head);

    // pass 3: weighted aggregate of h[src]; 512B coalesced gather per edge
    float4 acc = make_float4(0.f, 0.f, 0.f, 0.f);
    for (int base = 0; base < d; base += 32) {
        int jl = (base == 0) ? j0
                             : ((base + lane < d) ? g_srt[o0 + base + lane] : -1);
        int cnt = min(32, d - base);
        for (int t = 0; t < cnt; t++) {
            int j = __shfl_sync(0xffffffffu, jl, t);
            float asj = g_asrc[j * NH + head];
            float eh = lrelu(asj + adh);
            float al = __expf(eh - mh) * ih;
            float4 hv = *(const float4*)&g_h[(size_t)j * HC + lane * 4];
            acc.x = fmaf(al, hv.x, acc.x);
            acc.y = fmaf(al, hv.y, acc.y);
            acc.z = fmaf(al, hv.z, acc.z);
            acc.w = fmaf(al, hv.w, acc.w);
        }
    }
    float4 b = *(const float4*)&bias[lane * 4];
    float4 o = make_float4(acc.x + b.x, acc.y + b.y, acc.z + b.z, acc.w + b.w);
    *(float4*)&out[(size_t)w * HC + lane * 4] = o;
}

// ---------------- launch ----------------------------------------------------
extern "C" void kernel_launch(void* const* d_in, const int* in_sizes, int n_in,
                              void* d_out, int out_size)
{
    const float* x     = (const float*)d_in[0];
    const int*   ei    = (const int*)d_in[1];
    const float* W     = (const float*)d_in[2];
    const float* att_s = (const float*)d_in[3];
    const float* att_d = (const float*)d_in[4];
    const float* bias  = (const float*)d_in[5];
    float* out = (float*)d_out;

    const int NB = (NN + 1023) / 1024;   // 98

    cudaFuncSetAttribute(k_gemm, cudaFuncAttributeMaxDynamicSharedMemorySize, SO_TOT);

    k_init_deg<<<(NN + 255) / 256, 256>>>();
    k_hist<<<(NE + 255) / 256, 256>>>(ei);
    k_prepw<<<(HC * FF + 255) / 256, 256>>>(W);
    k_scan1<<<NB, 1024>>>();
    k_scan2<<<1, 128>>>();
    k_scan3<<<(NN + 255) / 256, 256>>>();
    k_fill<<<(NET + 255) / 256, 256>>>(ei);

    k_gemm<<<(NN + 63) / 64, 256, SO_TOT>>>(x, att_s, att_d);
    k_gat<<<(NN * 32 + 255) / 256, 256>>>(bias, out);
}